// round 3
// baseline (speedup 1.0000x reference)
#include <cuda_runtime.h>
#include <cuda_bf16.h>
#include <cstdint>

// Problem constants
constexpr int Bc  = 2;
constexpr int Lc  = 2048;
constexpr int Dc  = 768;
constexpr int Hc  = 12;
constexpr int HDc = 64;
constexpr int BH  = Bc * Hc;            // 24
constexpr int Mrows = Bc * Lc;          // 4096

// Scratch (device globals; no allocation allowed)
__device__ __align__(128) float g_q[(size_t)BH * Lc * HDc];   // [b,h,l,d]
__device__ __align__(128) float g_k[(size_t)BH * Lc * HDc];
__device__ __align__(128) float g_v[(size_t)BH * Lc * HDc];
__device__ __align__(128) float g_o[(size_t)Bc * Lc * Dc];    // [b,l,h*64+d]

__device__ __forceinline__ float silu_f(float x) {
    return x / (1.0f + __expf(-x));
}

__device__ __forceinline__ uint32_t f2tf(float x) {
    uint32_t r;
    asm("cvt.rna.tf32.f32 %0, %1;" : "=r"(r) : "f"(x));
    return r;
}

__device__ __forceinline__ uint32_t s2u(const void* p) {
    return (uint32_t)__cvta_generic_to_shared(p);
}

__device__ __forceinline__ void lm4(uint32_t& r0, uint32_t& r1,
                                    uint32_t& r2, uint32_t& r3, uint32_t addr) {
    asm volatile("ldmatrix.sync.aligned.m8n8.x4.shared.b16 {%0,%1,%2,%3},[%4];"
                 : "=r"(r0), "=r"(r1), "=r"(r2), "=r"(r3) : "r"(addr));
}

__device__ __forceinline__ void lm2(uint32_t& r0, uint32_t& r1, uint32_t addr) {
    asm volatile("ldmatrix.sync.aligned.m8n8.x2.shared.b16 {%0,%1},[%2];"
                 : "=r"(r0), "=r"(r1) : "r"(addr));
}

__device__ __forceinline__ void mma_tf32(float c[4],
                                         uint32_t a0, uint32_t a1, uint32_t a2, uint32_t a3,
                                         uint32_t b0, uint32_t b1) {
    asm volatile(
        "mma.sync.aligned.m16n8k8.row.col.f32.tf32.tf32.f32 "
        "{%0,%1,%2,%3},{%4,%5,%6,%7},{%8,%9},{%0,%1,%2,%3};"
        : "+f"(c[0]), "+f"(c[1]), "+f"(c[2]), "+f"(c[3])
        : "r"(a0), "r"(a1), "r"(a2), "r"(a3), "r"(b0), "r"(b1));
}

// ---------------------------------------------------------------------------
// tf32 GEMM: C[M,N] = A[M,768] * B[N,768]^T.  128x128 tile, BK=32, 8 warps.
// Fragments loaded with ldmatrix (b16 x4/x2 trick on tf32 data).
// MODE 1: A=hidden, B from {Wq,Wk,Wv} by tile, SiLU, scatter to g_q/k/v.
// MODE 0: A=g_o, B=Wo, plain write to Cout.
// ---------------------------------------------------------------------------
constexpr int GLD = 36;                       // smem row pitch (floats)
constexpr int GEMM_SMEM = 4 * 128 * GLD * 4;  // 73728 B

template<int MODE>
__global__ __launch_bounds__(256, 1)
void gemm_tf32_kernel(const float* __restrict__ Ain,
                      const float* __restrict__ B0,
                      const float* __restrict__ B1,
                      const float* __restrict__ B2,
                      float* __restrict__ Cout) {
    extern __shared__ uint32_t sm[];
    uint32_t* As = sm;                 // [2][128*GLD]
    uint32_t* Bs = sm + 2 * 128 * GLD;

    const int tid = threadIdx.x;
    const int warp = tid >> 5, lane = tid & 31;
    const int gr = lane >> 2, gc = lane & 3;
    const int m0 = blockIdx.y * 128;
    const int n0g = blockIdx.x * 128;

    const float* A = (MODE == 0) ? g_o : Ain;
    const float* Bp;
    int n0;
    int which = 0;
    if (MODE == 1) {
        which = n0g / Dc;
        Bp = (which == 0) ? B0 : (which == 1) ? B1 : B2;
        n0 = n0g % Dc;
    } else {
        Bp = B0;
        n0 = n0g;
    }

    const int warp_m0 = (warp >> 2) * 64;   // 2 warps in m
    const int warp_n0 = (warp & 3) * 32;    // 4 warps in n

    // ldmatrix lane-address offsets (bytes)
    const uint32_t laneA = ((lane & 15) * GLD + 4 * (lane >> 4)) * 4;
    const uint32_t laneB = ((lane & 7) * GLD + 4 * ((lane >> 3) & 1)) * 4;
    const uint32_t AsU = s2u(As), BsU = s2u(Bs);

    float4 ra[4], rb[4];

    auto load_regs = [&](int kt) {
#pragma unroll
        for (int i = 0; i < 4; i++) {
            const int idx = tid + i * 256;
            const int r = idx >> 3;
            const int c4 = (idx & 7) << 2;
            ra[i] = *(const float4*)&A [(size_t)(m0 + r) * Dc + kt * 32 + c4];
            rb[i] = *(const float4*)&Bp[(size_t)(n0 + r) * Dc + kt * 32 + c4];
        }
    };
    auto store_smem = [&](int buf) {
        uint32_t* Ab = As + buf * 128 * GLD;
        uint32_t* Bb = Bs + buf * 128 * GLD;
#pragma unroll
        for (int i = 0; i < 4; i++) {
            const int idx = tid + i * 256;
            const int r = idx >> 3;
            const int c4 = (idx & 7) << 2;
            *(uint4*)&Ab[r * GLD + c4] =
                make_uint4(f2tf(ra[i].x), f2tf(ra[i].y), f2tf(ra[i].z), f2tf(ra[i].w));
            *(uint4*)&Bb[r * GLD + c4] =
                make_uint4(f2tf(rb[i].x), f2tf(rb[i].y), f2tf(rb[i].z), f2tf(rb[i].w));
        }
    };

    float c[4][4][4] = {};

    load_regs(0);
    store_smem(0);
    __syncthreads();

    for (int kt = 0; kt < 24; kt++) {
        const int cur = kt & 1;
        if (kt < 23) load_regs(kt + 1);
        const uint32_t AbU = AsU + cur * 128 * GLD * 4;
        const uint32_t BbU = BsU + cur * 128 * GLD * 4;
#pragma unroll
        for (int kk = 0; kk < 4; kk++) {
            const int klo = kk * 8;
            uint32_t a[4][4], b[4][2];
#pragma unroll
            for (int mt = 0; mt < 4; mt++)
                lm4(a[mt][0], a[mt][1], a[mt][2], a[mt][3],
                    AbU + ((warp_m0 + mt * 16) * GLD + klo) * 4 + laneA);
#pragma unroll
            for (int nt = 0; nt < 4; nt++)
                lm2(b[nt][0], b[nt][1],
                    BbU + ((warp_n0 + nt * 8) * GLD + klo) * 4 + laneB);
#pragma unroll
            for (int mt = 0; mt < 4; mt++)
#pragma unroll
                for (int nt = 0; nt < 4; nt++)
                    mma_tf32(c[mt][nt], a[mt][0], a[mt][1], a[mt][2], a[mt][3],
                             b[nt][0], b[nt][1]);
        }
        if (kt < 23) store_smem(cur ^ 1);
        __syncthreads();
    }

    if (MODE == 0) {
#pragma unroll
        for (int mt = 0; mt < 4; mt++)
#pragma unroll
            for (int nt = 0; nt < 4; nt++) {
                const int row = m0 + warp_m0 + mt * 16 + gr;
                const int col = n0 + warp_n0 + nt * 8 + 2 * gc;
                Cout[(size_t)(row    ) * Dc + col    ] = c[mt][nt][0];
                Cout[(size_t)(row    ) * Dc + col + 1] = c[mt][nt][1];
                Cout[(size_t)(row + 8) * Dc + col    ] = c[mt][nt][2];
                Cout[(size_t)(row + 8) * Dc + col + 1] = c[mt][nt][3];
            }
    } else {
        float* dst = (which == 0) ? g_q : (which == 1) ? g_k : g_v;
#pragma unroll
        for (int mt = 0; mt < 4; mt++)
#pragma unroll
            for (int nt = 0; nt < 4; nt++)
#pragma unroll
                for (int half = 0; half < 2; half++)
#pragma unroll
                    for (int e = 0; e < 2; e++) {
                        const int row = m0 + warp_m0 + mt * 16 + half * 8 + gr;
                        const int colL = n0 + warp_n0 + nt * 8 + 2 * gc + e;
                        const int h = colL >> 6, d = colL & 63;
                        const int b = row >> 11, l = row & 2047;
                        dst[(((size_t)b * Hc + h) * Lc + l) * HDc + d] =
                            silu_f(c[mt][nt][half * 2 + e]);
                    }
    }
}

// ---------------------------------------------------------------------------
// Kernel 2: in-place RoPE on g_q and g_k (fp32 exact).
// ---------------------------------------------------------------------------
__global__ void rope_kernel(const float* __restrict__ cosp,
                            const float* __restrict__ sinp) {
    const int idx = blockIdx.x * blockDim.x + threadIdx.x;
    const int pair = idx & 31;
    const int t = idx >> 5;
    const int nrows = BH * Lc;
    const int which = t / nrows;
    const int row = t % nrows;
    float* p = which ? g_k : g_q;

    const int l = row % Lc;
    const int b = (row / Lc) / Hc;

    const size_t cbase = ((size_t)b * Lc + l) * HDc;
    const float c1 = cosp[cbase + pair];
    const float c2 = cosp[cbase + pair + 32];
    const float s1 = sinp[cbase + pair];
    const float s2 = sinp[cbase + pair + 32];

    const size_t base = (size_t)row * HDc;
    const float x1 = p[base + pair];
    const float x2 = p[base + pair + 32];
    p[base + pair]      = x1 * c1 - x2 * s1;
    p[base + pair + 32] = x2 * c2 + x1 * s2;
}

// ---------------------------------------------------------------------------
// Kernel 3: causal attention, tensor-core tf32.
// Block = one (b,h), one 128-row q-tile, 8 warps (4m x 2n), warp tile 32x32.
// Q fragments preloaded in registers. K/V/S frags via ldmatrix.
// Long blocks (high qt) scheduled first.
// ---------------------------------------------------------------------------
constexpr int ALD = 68;                          // smem row pitch (floats)
constexpr int ATTN_SMEM = (64 + 64 + 128) * ALD * 4;  // Ks,Vt,Ss = 69632 B

__global__ __launch_bounds__(256, 1)
void attn_mma_kernel(float* __restrict__ attn_out) {
    extern __shared__ uint32_t sm[];
    uint32_t* Ks = sm;                    // [64][ALD] tf32
    uint32_t* Vt = Ks + 64 * ALD;         // [d=64][ALD] tf32, transposed
    float*    Ss = (float*)(Vt + 64 * ALD);   // [128][ALD] f32 (Q tf32 at start)

    const int tid = threadIdx.x;
    const int warp = tid >> 5, lane = tid & 31;
    const int gr = lane >> 2, gc = lane & 3;
    const int bh = blockIdx.y;
    const int qt = (int)gridDim.x - 1 - (int)blockIdx.x;   // long blocks first
    const int q0 = qt * 128;

    const int warp_m0 = (warp >> 1) * 32;   // 4 warps in m (q rows)
    const int warp_n0 = (warp & 1) * 32;    // 2 warps in n

    const uint32_t laneA = ((lane & 15) * ALD + 4 * (lane >> 4)) * 4;
    const uint32_t laneB = ((lane & 7) * ALD + 4 * ((lane >> 3) & 1)) * 4;
    const uint32_t KsU = s2u(Ks), VtU = s2u(Vt), SsU = s2u(Ss);

    const float* Qg = g_q + (size_t)bh * Lc * HDc;
    const float* Kg = g_k + (size_t)bh * Lc * HDc;
    const float* Vg = g_v + (size_t)bh * Lc * HDc;
    float* attn_base = attn_out + (size_t)bh * Lc * Lc;

    // Stage Q (tf32) into Ss area, then preload all Q fragments to registers.
#pragma unroll
    for (int i = 0; i < 8; i++) {
        const int idx = tid + i * 256;
        const int r = idx >> 4;
        const int c4 = (idx & 15) << 2;
        float4 v = *(const float4*)&Qg[(size_t)(q0 + r) * HDc + c4];
        *(uint4*)&((uint32_t*)Ss)[r * ALD + c4] =
            make_uint4(f2tf(v.x), f2tf(v.y), f2tf(v.z), f2tf(v.w));
    }
    __syncthreads();

    uint32_t qf[2][8][4];
#pragma unroll
    for (int mt = 0; mt < 2; mt++)
#pragma unroll
        for (int kk = 0; kk < 8; kk++)
            lm4(qf[mt][kk][0], qf[mt][kk][1], qf[mt][kk][2], qf[mt][kk][3],
                SsU + ((warp_m0 + mt * 16) * ALD + kk * 8) * 4 + laneA);
    __syncthreads();

    float o[2][4][4] = {};
    const int ktn = 2 * qt + 2;

    for (int kt = 0; kt < ktn; kt++) {
        if (kt > 0) __syncthreads();       // prior SV-mma reads done
        // Stage K (row-major tf32)
#pragma unroll
        for (int i = 0; i < 4; i++) {
            const int idx = tid + i * 256;
            const int r = idx >> 4;
            const int c4 = (idx & 15) << 2;
            float4 kv = *(const float4*)&Kg[(size_t)(kt * 64 + r) * HDc + c4];
            *(uint4*)&Ks[r * ALD + c4] =
                make_uint4(f2tf(kv.x), f2tf(kv.y), f2tf(kv.z), f2tf(kv.w));
        }
        // Stage V transposed: Vt[d][k]. lane->d mapping keeps STS conflict-free.
#pragma unroll
        for (int i = 0; i < 4; i++) {
            const int idx = tid + i * 256;
            const int d = idx & 63;
            const int rg = idx >> 6;          // 0..15, k-base = 4*rg
            const int kb = kt * 64 + rg * 4;
            uint4 vv;
            vv.x = f2tf(Vg[(size_t)(kb + 0) * HDc + d]);
            vv.y = f2tf(Vg[(size_t)(kb + 1) * HDc + d]);
            vv.z = f2tf(Vg[(size_t)(kb + 2) * HDc + d]);
            vv.w = f2tf(Vg[(size_t)(kb + 3) * HDc + d]);
            *(uint4*)&Vt[d * ALD + rg * 4] = vv;
        }
        __syncthreads();

        // S = Q K^T  (warp tile 32x32)
        float s[2][4][4] = {};
#pragma unroll
        for (int kk = 0; kk < 8; kk++) {
            uint32_t b[4][2];
#pragma unroll
            for (int nt = 0; nt < 4; nt++)
                lm2(b[nt][0], b[nt][1],
                    KsU + ((warp_n0 + nt * 8) * ALD + kk * 8) * 4 + laneB);
#pragma unroll
            for (int mt = 0; mt < 2; mt++)
#pragma unroll
                for (int nt = 0; nt < 4; nt++)
                    mma_tf32(s[mt][nt], qf[mt][kk][0], qf[mt][kk][1],
                             qf[mt][kk][2], qf[mt][kk][3], b[nt][0], b[nt][1]);
        }

        // mask + silu/L -> Ss
#pragma unroll
        for (int mt = 0; mt < 2; mt++)
#pragma unroll
            for (int nt = 0; nt < 4; nt++)
#pragma unroll
                for (int half = 0; half < 2; half++)
#pragma unroll
                    for (int e = 0; e < 2; e++) {
                        const int row = warp_m0 + mt * 16 + half * 8 + gr;
                        const int col = warp_n0 + nt * 8 + 2 * gc + e;
                        const int q = q0 + row;
                        const int k = kt * 64 + col;
                        const float x = s[mt][nt][half * 2 + e];
                        Ss[row * ALD + col] =
                            (k <= q) ? silu_f(x) * (1.0f / Lc) : 0.0f;
                    }
        __syncthreads();

        // attn gmem write (float4)
#pragma unroll
        for (int i = 0; i < 8; i++) {
            const int idx = tid + i * 256;
            const int r = idx >> 4;
            const int c4 = (idx & 15) << 2;
            *(float4*)&attn_base[(size_t)(q0 + r) * Lc + kt * 64 + c4] =
                *(const float4*)&Ss[r * ALD + c4];
        }

        // O += S @ V   (A frags from Ss via ldmatrix + cvt, B from Vt)
#pragma unroll
        for (int kk = 0; kk < 8; kk++) {
            const int klo = kk * 8;
            uint32_t a[2][4], b[4][2];
#pragma unroll
            for (int mt = 0; mt < 2; mt++) {
                lm4(a[mt][0], a[mt][1], a[mt][2], a[mt][3],
                    SsU + ((warp_m0 + mt * 16) * ALD + klo) * 4 + laneA);
#pragma unroll
                for (int j = 0; j < 4; j++)
                    a[mt][j] = f2tf(__uint_as_float(a[mt][j]));
            }
#pragma unroll
            for (int nt = 0; nt < 4; nt++)
                lm2(b[nt][0], b[nt][1],
                    VtU + ((warp_n0 + nt * 8) * ALD + klo) * 4 + laneB);
#pragma unroll
            for (int mt = 0; mt < 2; mt++)
#pragma unroll
                for (int nt = 0; nt < 4; nt++)
                    mma_tf32(o[mt][nt], a[mt][0], a[mt][1], a[mt][2], a[mt][3],
                             b[nt][0], b[nt][1]);
        }
    }

    // Zero-fill strictly-upper region (k >= q0+128)
    const int zstart = q0 + 128;
    const int zcols = Lc - zstart;
    if (zcols > 0) {
        const int row4 = zcols >> 2;
        const int tot4 = 128 * row4;
        for (int e = tid; e < tot4; e += 256) {
            const int row = e / row4;
            const int c4 = (e % row4) << 2;
            *(float4*)&attn_base[(size_t)(q0 + row) * Lc + zstart + c4] =
                make_float4(0.f, 0.f, 0.f, 0.f);
        }
    }

    // Write O into [b][l][h*64+d]
    const int b = bh / Hc;
    const int h = bh % Hc;
#pragma unroll
    for (int mt = 0; mt < 2; mt++)
#pragma unroll
        for (int nt = 0; nt < 4; nt++)
#pragma unroll
            for (int half = 0; half < 2; half++)
#pragma unroll
                for (int e = 0; e < 2; e++) {
                    const int row = q0 + warp_m0 + mt * 16 + half * 8 + gr;
                    const int d = warp_n0 + nt * 8 + 2 * gc + e;
                    g_o[((size_t)b * Lc + row) * Dc + h * HDc + d] =
                        o[mt][nt][half * 2 + e];
                }
}

// ---------------------------------------------------------------------------
// Launch. Inputs: hidden_states, attention_mask, cos, sin, Wq, Wk, Wv, Wo.
// Output: [attn_output (B*L*D) | attn (B*H*L*L)]. Mask handled analytically.
// ---------------------------------------------------------------------------
extern "C" void kernel_launch(void* const* d_in, const int* in_sizes, int n_in,
                              void* d_out, int out_size) {
    const float* hidden = (const float*)d_in[0];
    const float* cosp   = (const float*)d_in[2];
    const float* sinp   = (const float*)d_in[3];
    const float* Wq     = (const float*)d_in[4];
    const float* Wk     = (const float*)d_in[5];
    const float* Wv     = (const float*)d_in[6];
    const float* Wo     = (const float*)d_in[7];

    float* out = (float*)d_out;
    float* attn_out = out + (size_t)Bc * Lc * Dc;

    cudaFuncSetAttribute(gemm_tf32_kernel<1>,
                         cudaFuncAttributeMaxDynamicSharedMemorySize, GEMM_SMEM);
    cudaFuncSetAttribute(gemm_tf32_kernel<0>,
                         cudaFuncAttributeMaxDynamicSharedMemorySize, GEMM_SMEM);
    cudaFuncSetAttribute(attn_mma_kernel,
                         cudaFuncAttributeMaxDynamicSharedMemorySize, ATTN_SMEM);

    // 1) QKV projections + SiLU (tensor core tf32)
    gemm_tf32_kernel<1><<<dim3(3 * Dc / 128, Mrows / 128), 256, GEMM_SMEM>>>(
        hidden, Wq, Wk, Wv, nullptr);

    // 2) RoPE on q,k
    {
        const int total = 2 * BH * Lc * 32;
        rope_kernel<<<total / 256, 256>>>(cosp, sinp);
    }

    // 3) Attention (128-row q tiles, reversed schedule)
    attn_mma_kernel<<<dim3(Lc / 128, BH), 256, ATTN_SMEM>>>(attn_out);

    // 4) Output projection
    gemm_tf32_kernel<0><<<dim3(Dc / 128, Mrows / 128), 256, GEMM_SMEM>>>(
        nullptr, Wo, nullptr, nullptr, out);
}

// round 4
// speedup vs baseline: 1.2516x; 1.2516x over previous
#include <cuda_runtime.h>
#include <cuda_bf16.h>
#include <cstdint>

// Problem constants
constexpr int Bc  = 2;
constexpr int Lc  = 2048;
constexpr int Dc  = 768;
constexpr int Hc  = 12;
constexpr int HDc = 64;
constexpr int BH  = Bc * Hc;            // 24
constexpr int Mrows = Bc * Lc;          // 4096

// Scratch (device globals; no allocation allowed)
__device__ __align__(128) float g_q[(size_t)BH * Lc * HDc];   // [b,h,l,d]
__device__ __align__(128) float g_k[(size_t)BH * Lc * HDc];
__device__ __align__(128) float g_v[(size_t)BH * Lc * HDc];
__device__ __align__(128) float g_o[(size_t)Bc * Lc * Dc];    // [b,l,h*64+d]

__device__ __forceinline__ float silu_f(float x) {
    return x / (1.0f + __expf(-x));
}

__device__ __forceinline__ uint32_t f2tf(float x) {
    uint32_t r;
    asm("cvt.rna.tf32.f32 %0, %1;" : "=r"(r) : "f"(x));
    return r;
}

__device__ __forceinline__ uint32_t s2u(const void* p) {
    return (uint32_t)__cvta_generic_to_shared(p);
}

__device__ __forceinline__ void lm4(uint32_t& r0, uint32_t& r1,
                                    uint32_t& r2, uint32_t& r3, uint32_t addr) {
    asm volatile("ldmatrix.sync.aligned.m8n8.x4.shared.b16 {%0,%1,%2,%3},[%4];"
                 : "=r"(r0), "=r"(r1), "=r"(r2), "=r"(r3) : "r"(addr));
}

__device__ __forceinline__ void lm2(uint32_t& r0, uint32_t& r1, uint32_t addr) {
    asm volatile("ldmatrix.sync.aligned.m8n8.x2.shared.b16 {%0,%1},[%2];"
                 : "=r"(r0), "=r"(r1) : "r"(addr));
}

__device__ __forceinline__ void mma_tf32(float c[4],
                                         uint32_t a0, uint32_t a1, uint32_t a2, uint32_t a3,
                                         uint32_t b0, uint32_t b1) {
    asm volatile(
        "mma.sync.aligned.m16n8k8.row.col.f32.tf32.tf32.f32 "
        "{%0,%1,%2,%3},{%4,%5,%6,%7},{%8,%9},{%0,%1,%2,%3};"
        : "+f"(c[0]), "+f"(c[1]), "+f"(c[2]), "+f"(c[3])
        : "r"(a0), "r"(a1), "r"(a2), "r"(a3), "r"(b0), "r"(b1));
}

// ---------------------------------------------------------------------------
// tf32 GEMM: C[M,N] = A[M,768] * B[N,768]^T.  128x128 tile, BK=32.
// 512 threads / 16 warps (4m x 4n, warp tile 32x32) for 4 warps/SMSP.
// MODE 1: A=hidden, B from {Wq,Wk,Wv} by tile, SiLU, scatter to g_q/k/v.
// MODE 0: A=g_o, B=Wo, plain write to Cout.
// ---------------------------------------------------------------------------
constexpr int GLD = 36;                       // smem row pitch (floats)
constexpr int GEMM_SMEM = 4 * 128 * GLD * 4;  // 73728 B

template<int MODE>
__global__ __launch_bounds__(512, 1)
void gemm_tf32_kernel(const float* __restrict__ Ain,
                      const float* __restrict__ B0,
                      const float* __restrict__ B1,
                      const float* __restrict__ B2,
                      float* __restrict__ Cout) {
    extern __shared__ uint32_t sm[];
    uint32_t* As = sm;                 // [2][128*GLD]
    uint32_t* Bs = sm + 2 * 128 * GLD;

    const int tid = threadIdx.x;
    const int warp = tid >> 5, lane = tid & 31;
    const int gr = lane >> 2, gc = lane & 3;
    const int m0 = blockIdx.y * 128;
    const int n0g = blockIdx.x * 128;

    const float* A = (MODE == 0) ? g_o : Ain;
    const float* Bp;
    int n0;
    int which = 0;
    if (MODE == 1) {
        which = n0g / Dc;
        Bp = (which == 0) ? B0 : (which == 1) ? B1 : B2;
        n0 = n0g % Dc;
    } else {
        Bp = B0;
        n0 = n0g;
    }

    const int warp_m0 = (warp >> 2) * 32;   // 4 warps in m
    const int warp_n0 = (warp & 3) * 32;    // 4 warps in n

    const uint32_t laneA = ((lane & 15) * GLD + 4 * (lane >> 4)) * 4;
    const uint32_t laneB = ((lane & 7) * GLD + 4 * ((lane >> 3) & 1)) * 4;
    const uint32_t AsU = s2u(As), BsU = s2u(Bs);

    float4 ra[2], rb[2];

    auto load_regs = [&](int kt) {
#pragma unroll
        for (int i = 0; i < 2; i++) {
            const int idx = tid + i * 512;
            const int r = idx >> 3;               // 0..127
            const int c4 = (idx & 7) << 2;
            ra[i] = *(const float4*)&A [(size_t)(m0 + r) * Dc + kt * 32 + c4];
            rb[i] = *(const float4*)&Bp[(size_t)(n0 + r) * Dc + kt * 32 + c4];
        }
    };
    auto store_smem = [&](int buf) {
        uint32_t* Ab = As + buf * 128 * GLD;
        uint32_t* Bb = Bs + buf * 128 * GLD;
#pragma unroll
        for (int i = 0; i < 2; i++) {
            const int idx = tid + i * 512;
            const int r = idx >> 3;
            const int c4 = (idx & 7) << 2;
            *(uint4*)&Ab[r * GLD + c4] =
                make_uint4(f2tf(ra[i].x), f2tf(ra[i].y), f2tf(ra[i].z), f2tf(ra[i].w));
            *(uint4*)&Bb[r * GLD + c4] =
                make_uint4(f2tf(rb[i].x), f2tf(rb[i].y), f2tf(rb[i].z), f2tf(rb[i].w));
        }
    };

    float c[2][4][4] = {};     // [mt][nt][frag]

    load_regs(0);
    store_smem(0);
    __syncthreads();

    for (int kt = 0; kt < 24; kt++) {
        const int cur = kt & 1;
        if (kt < 23) load_regs(kt + 1);
        const uint32_t AbU = AsU + cur * 128 * GLD * 4;
        const uint32_t BbU = BsU + cur * 128 * GLD * 4;
#pragma unroll
        for (int kk = 0; kk < 4; kk++) {
            const int klo = kk * 8;
            uint32_t a[2][4], b[4][2];
#pragma unroll
            for (int mt = 0; mt < 2; mt++)
                lm4(a[mt][0], a[mt][1], a[mt][2], a[mt][3],
                    AbU + ((warp_m0 + mt * 16) * GLD + klo) * 4 + laneA);
#pragma unroll
            for (int nt = 0; nt < 4; nt++)
                lm2(b[nt][0], b[nt][1],
                    BbU + ((warp_n0 + nt * 8) * GLD + klo) * 4 + laneB);
#pragma unroll
            for (int mt = 0; mt < 2; mt++)
#pragma unroll
                for (int nt = 0; nt < 4; nt++)
                    mma_tf32(c[mt][nt], a[mt][0], a[mt][1], a[mt][2], a[mt][3],
                             b[nt][0], b[nt][1]);
        }
        if (kt < 23) store_smem(cur ^ 1);
        __syncthreads();
    }

    if (MODE == 0) {
#pragma unroll
        for (int mt = 0; mt < 2; mt++)
#pragma unroll
            for (int nt = 0; nt < 4; nt++) {
                const int row = m0 + warp_m0 + mt * 16 + gr;
                const int col = n0 + warp_n0 + nt * 8 + 2 * gc;
                Cout[(size_t)(row    ) * Dc + col    ] = c[mt][nt][0];
                Cout[(size_t)(row    ) * Dc + col + 1] = c[mt][nt][1];
                Cout[(size_t)(row + 8) * Dc + col    ] = c[mt][nt][2];
                Cout[(size_t)(row + 8) * Dc + col + 1] = c[mt][nt][3];
            }
    } else {
        float* dst = (which == 0) ? g_q : (which == 1) ? g_k : g_v;
#pragma unroll
        for (int mt = 0; mt < 2; mt++)
#pragma unroll
            for (int nt = 0; nt < 4; nt++)
#pragma unroll
                for (int half = 0; half < 2; half++)
#pragma unroll
                    for (int e = 0; e < 2; e++) {
                        const int row = m0 + warp_m0 + mt * 16 + half * 8 + gr;
                        const int colL = n0 + warp_n0 + nt * 8 + 2 * gc + e;
                        const int h = colL >> 6, d = colL & 63;
                        const int b = row >> 11, l = row & 2047;
                        dst[(((size_t)b * Hc + h) * Lc + l) * HDc + d] =
                            silu_f(c[mt][nt][half * 2 + e]);
                    }
    }
}

// ---------------------------------------------------------------------------
// Kernel 2: in-place RoPE on g_q and g_k (fp32 exact).
// ---------------------------------------------------------------------------
__global__ void rope_kernel(const float* __restrict__ cosp,
                            const float* __restrict__ sinp) {
    const int idx = blockIdx.x * blockDim.x + threadIdx.x;
    const int pair = idx & 31;
    const int t = idx >> 5;
    const int nrows = BH * Lc;
    const int which = t / nrows;
    const int row = t % nrows;
    float* p = which ? g_k : g_q;

    const int l = row % Lc;
    const int b = (row / Lc) / Hc;

    const size_t cbase = ((size_t)b * Lc + l) * HDc;
    const float c1 = cosp[cbase + pair];
    const float c2 = cosp[cbase + pair + 32];
    const float s1 = sinp[cbase + pair];
    const float s2 = sinp[cbase + pair + 32];

    const size_t base = (size_t)row * HDc;
    const float x1 = p[base + pair];
    const float x2 = p[base + pair + 32];
    p[base + pair]      = x1 * c1 - x2 * s1;
    p[base + pair + 32] = x2 * c2 + x1 * s2;
}

// ---------------------------------------------------------------------------
// Kernel 3: causal attention, tensor-core tf32.
// Block = one (b,h), one 128-row q-tile, 512 threads / 16 warps (8m x 2n),
// warp tile 16x32. Q fragments preloaded. 1D grid, qt descending.
// ---------------------------------------------------------------------------
constexpr int ALD = 68;                          // smem row pitch (floats)
constexpr int ATTN_SMEM = (64 + 64 + 128) * ALD * 4;  // Ks,Vt,Ss = 69632 B
constexpr int QTILES = Lc / 128;                 // 16

__global__ __launch_bounds__(512, 1)
void attn_mma_kernel(float* __restrict__ attn_out) {
    extern __shared__ uint32_t sm[];
    uint32_t* Ks = sm;                    // [64][ALD] tf32
    uint32_t* Vt = Ks + 64 * ALD;         // [d=64][ALD] tf32, transposed
    float*    Ss = (float*)(Vt + 64 * ALD);   // [128][ALD] f32

    const int tid = threadIdx.x;
    const int warp = tid >> 5, lane = tid & 31;
    const int gr = lane >> 2, gc = lane & 3;
    // qt descending primary order: heavy blocks first across all bh.
    const int qt = QTILES - 1 - (int)blockIdx.x / BH;
    const int bh = (int)blockIdx.x % BH;
    const int q0 = qt * 128;

    const int warp_m0 = (warp >> 1) * 16;   // 8 warps in m (q rows)
    const int warp_n0 = (warp & 1) * 32;    // 2 warps in n

    const uint32_t laneA = ((lane & 15) * ALD + 4 * (lane >> 4)) * 4;
    const uint32_t laneB = ((lane & 7) * ALD + 4 * ((lane >> 3) & 1)) * 4;
    const uint32_t KsU = s2u(Ks), VtU = s2u(Vt), SsU = s2u(Ss);

    const float* Qg = g_q + (size_t)bh * Lc * HDc;
    const float* Kg = g_k + (size_t)bh * Lc * HDc;
    const float* Vg = g_v + (size_t)bh * Lc * HDc;
    float* attn_base = attn_out + (size_t)bh * Lc * Lc;

    // Stage Q (tf32) into Ss area, then preload Q fragments to registers.
#pragma unroll
    for (int i = 0; i < 4; i++) {
        const int idx = tid + i * 512;
        const int r = idx >> 4;
        const int c4 = (idx & 15) << 2;
        float4 v = *(const float4*)&Qg[(size_t)(q0 + r) * HDc + c4];
        *(uint4*)&((uint32_t*)Ss)[r * ALD + c4] =
            make_uint4(f2tf(v.x), f2tf(v.y), f2tf(v.z), f2tf(v.w));
    }
    __syncthreads();

    uint32_t qf[8][4];
#pragma unroll
    for (int kk = 0; kk < 8; kk++)
        lm4(qf[kk][0], qf[kk][1], qf[kk][2], qf[kk][3],
            SsU + (warp_m0 * ALD + kk * 8) * 4 + laneA);
    __syncthreads();

    float o[4][4] = {};
    const int ktn = 2 * qt + 2;

    for (int kt = 0; kt < ktn; kt++) {
        if (kt > 0) __syncthreads();       // prior SV-mma reads done
        // Stage K (row-major tf32): 64x64 -> 2 float4/thread
#pragma unroll
        for (int i = 0; i < 2; i++) {
            const int idx = tid + i * 512;
            const int r = idx >> 4;
            const int c4 = (idx & 15) << 2;
            float4 kv = *(const float4*)&Kg[(size_t)(kt * 64 + r) * HDc + c4];
            *(uint4*)&Ks[r * ALD + c4] =
                make_uint4(f2tf(kv.x), f2tf(kv.y), f2tf(kv.z), f2tf(kv.w));
        }
        // Stage V transposed: Vt[d][k], conflict-free (lane -> d).
#pragma unroll
        for (int i = 0; i < 2; i++) {
            const int idx = tid + i * 512;
            const int d = idx & 63;
            const int rg = idx >> 6;          // 0..15
            const int kb = kt * 64 + rg * 4;
            uint4 vv;
            vv.x = f2tf(Vg[(size_t)(kb + 0) * HDc + d]);
            vv.y = f2tf(Vg[(size_t)(kb + 1) * HDc + d]);
            vv.z = f2tf(Vg[(size_t)(kb + 2) * HDc + d]);
            vv.w = f2tf(Vg[(size_t)(kb + 3) * HDc + d]);
            *(uint4*)&Vt[d * ALD + rg * 4] = vv;
        }
        __syncthreads();

        // S = Q K^T  (warp tile 16x32)
        float s[4][4] = {};
#pragma unroll
        for (int kk = 0; kk < 8; kk++) {
            uint32_t b[4][2];
#pragma unroll
            for (int nt = 0; nt < 4; nt++)
                lm2(b[nt][0], b[nt][1],
                    KsU + ((warp_n0 + nt * 8) * ALD + kk * 8) * 4 + laneB);
#pragma unroll
            for (int nt = 0; nt < 4; nt++)
                mma_tf32(s[nt], qf[kk][0], qf[kk][1], qf[kk][2], qf[kk][3],
                         b[nt][0], b[nt][1]);
        }

        // mask + silu/L -> Ss
#pragma unroll
        for (int nt = 0; nt < 4; nt++)
#pragma unroll
            for (int half = 0; half < 2; half++)
#pragma unroll
                for (int e = 0; e < 2; e++) {
                    const int row = warp_m0 + half * 8 + gr;
                    const int col = warp_n0 + nt * 8 + 2 * gc + e;
                    const int q = q0 + row;
                    const int k = kt * 64 + col;
                    const float x = s[nt][half * 2 + e];
                    Ss[row * ALD + col] =
                        (k <= q) ? silu_f(x) * (1.0f / Lc) : 0.0f;
                }
        __syncthreads();

        // attn gmem write (float4): 128x64 -> 4/thread
#pragma unroll
        for (int i = 0; i < 4; i++) {
            const int idx = tid + i * 512;
            const int r = idx >> 4;
            const int c4 = (idx & 15) << 2;
            *(float4*)&attn_base[(size_t)(q0 + r) * Lc + kt * 64 + c4] =
                *(const float4*)&Ss[r * ALD + c4];
        }

        // O += S @ V
#pragma unroll
        for (int kk = 0; kk < 8; kk++) {
            const int klo = kk * 8;
            uint32_t a[4], b[4][2];
            lm4(a[0], a[1], a[2], a[3],
                SsU + (warp_m0 * ALD + klo) * 4 + laneA);
#pragma unroll
            for (int j = 0; j < 4; j++)
                a[j] = f2tf(__uint_as_float(a[j]));
#pragma unroll
            for (int nt = 0; nt < 4; nt++)
                lm2(b[nt][0], b[nt][1],
                    VtU + ((warp_n0 + nt * 8) * ALD + klo) * 4 + laneB);
#pragma unroll
            for (int nt = 0; nt < 4; nt++)
                mma_tf32(o[nt], a[0], a[1], a[2], a[3], b[nt][0], b[nt][1]);
        }
    }

    // Zero-fill strictly-upper region (k >= q0+128)
    const int zstart = q0 + 128;
    const int zcols = Lc - zstart;
    if (zcols > 0) {
        const int row4 = zcols >> 2;
        const int tot4 = 128 * row4;
        for (int e = tid; e < tot4; e += 512) {
            const int row = e / row4;
            const int c4 = (e % row4) << 2;
            *(float4*)&attn_base[(size_t)(q0 + row) * Lc + zstart + c4] =
                make_float4(0.f, 0.f, 0.f, 0.f);
        }
    }

    // Write O into [b][l][h*64+d]
    const int b = bh / Hc;
    const int h = bh % Hc;
#pragma unroll
    for (int nt = 0; nt < 4; nt++)
#pragma unroll
        for (int half = 0; half < 2; half++)
#pragma unroll
            for (int e = 0; e < 2; e++) {
                const int row = q0 + warp_m0 + half * 8 + gr;
                const int d = warp_n0 + nt * 8 + 2 * gc + e;
                g_o[((size_t)b * Lc + row) * Dc + h * HDc + d] =
                    o[nt][half * 2 + e];
            }
}

// ---------------------------------------------------------------------------
// Launch. Inputs: hidden_states, attention_mask, cos, sin, Wq, Wk, Wv, Wo.
// Output: [attn_output (B*L*D) | attn (B*H*L*L)]. Mask handled analytically.
// ---------------------------------------------------------------------------
extern "C" void kernel_launch(void* const* d_in, const int* in_sizes, int n_in,
                              void* d_out, int out_size) {
    const float* hidden = (const float*)d_in[0];
    const float* cosp   = (const float*)d_in[2];
    const float* sinp   = (const float*)d_in[3];
    const float* Wq     = (const float*)d_in[4];
    const float* Wk     = (const float*)d_in[5];
    const float* Wv     = (const float*)d_in[6];
    const float* Wo     = (const float*)d_in[7];

    float* out = (float*)d_out;
    float* attn_out = out + (size_t)Bc * Lc * Dc;

    cudaFuncSetAttribute(gemm_tf32_kernel<1>,
                         cudaFuncAttributeMaxDynamicSharedMemorySize, GEMM_SMEM);
    cudaFuncSetAttribute(gemm_tf32_kernel<0>,
                         cudaFuncAttributeMaxDynamicSharedMemorySize, GEMM_SMEM);
    cudaFuncSetAttribute(attn_mma_kernel,
                         cudaFuncAttributeMaxDynamicSharedMemorySize, ATTN_SMEM);

    // 1) QKV projections + SiLU (tensor core tf32)
    gemm_tf32_kernel<1><<<dim3(3 * Dc / 128, Mrows / 128), 512, GEMM_SMEM>>>(
        hidden, Wq, Wk, Wv, nullptr);

    // 2) RoPE on q,k
    {
        const int total = 2 * BH * Lc * 32;
        rope_kernel<<<total / 256, 256>>>(cosp, sinp);
    }

    // 3) Attention (128-row q tiles, qt-descending 1D schedule)
    attn_mma_kernel<<<QTILES * BH, 512, ATTN_SMEM>>>(attn_out);

    // 4) Output projection
    gemm_tf32_kernel<0><<<dim3(Dc / 128, Mrows / 128), 512, GEMM_SMEM>>>(
        nullptr, Wo, nullptr, nullptr, out);
}

// round 9
// speedup vs baseline: 1.2593x; 1.0062x over previous
#include <cuda_runtime.h>
#include <cuda_bf16.h>
#include <cstdint>

// Problem constants
constexpr int Bc  = 2;
constexpr int Lc  = 2048;
constexpr int Dc  = 768;
constexpr int Hc  = 12;
constexpr int HDc = 64;
constexpr int BH  = Bc * Hc;            // 24
constexpr int Mrows = Bc * Lc;          // 4096

// Scratch (device globals; no allocation allowed)
__device__ __align__(128) float g_q[(size_t)BH * Lc * HDc];   // [b,h,l,d] tf32-rounded
__device__ __align__(128) float g_k[(size_t)BH * Lc * HDc];   // tf32-rounded
__device__ __align__(128) float g_v[(size_t)BH * Lc * HDc];   // tf32-rounded
__device__ __align__(128) float g_o[(size_t)Bc * Lc * Dc];    // [b,l,h*64+d] tf32-rounded
__device__ __align__(128) float g_hid_tf[(size_t)Mrows * Dc];   // rounded hidden
__device__ __align__(128) float g_w_tf[(size_t)3 * Dc * Dc];    // rounded Wq|Wk|Wv
__device__ __align__(128) float g_wo_tf[(size_t)Dc * Dc];       // rounded Wo

__device__ __forceinline__ float silu_f(float x) {
    return x / (1.0f + __expf(-x));
}

__device__ __forceinline__ uint32_t f2tf(float x) {
    uint32_t r;
    asm("cvt.rna.tf32.f32 %0, %1;" : "=r"(r) : "f"(x));
    return r;
}

__device__ __forceinline__ uint32_t s2u(const void* p) {
    return (uint32_t)__cvta_generic_to_shared(p);
}

__device__ __forceinline__ void lm4(uint32_t& r0, uint32_t& r1,
                                    uint32_t& r2, uint32_t& r3, uint32_t addr) {
    asm volatile("ldmatrix.sync.aligned.m8n8.x4.shared.b16 {%0,%1,%2,%3},[%4];"
                 : "=r"(r0), "=r"(r1), "=r"(r2), "=r"(r3) : "r"(addr));
}

__device__ __forceinline__ void mma_tf32(float c[4],
                                         uint32_t a0, uint32_t a1, uint32_t a2, uint32_t a3,
                                         uint32_t b0, uint32_t b1) {
    asm volatile(
        "mma.sync.aligned.m16n8k8.row.col.f32.tf32.tf32.f32 "
        "{%0,%1,%2,%3},{%4,%5,%6,%7},{%8,%9},{%0,%1,%2,%3};"
        : "+f"(c[0]), "+f"(c[1]), "+f"(c[2]), "+f"(c[3])
        : "r"(a0), "r"(a1), "r"(a2), "r"(a3), "r"(b0), "r"(b1));
}

__device__ __forceinline__ void cpa16(uint32_t s, const void* g) {
    asm volatile("cp.async.cg.shared.global [%0], [%1], 16;" :: "r"(s), "l"(g));
}

// ---------------------------------------------------------------------------
// Kernel 0: round fp32 -> tf32 (RNA) bit patterns, float4 elementwise.
// ---------------------------------------------------------------------------
__global__ void cvt_tf32_kernel(const float4* __restrict__ src,
                                float4* __restrict__ dst, int n4) {
    int i = blockIdx.x * blockDim.x + threadIdx.x;
    if (i < n4) {
        float4 v = src[i];
        float4 w;
        w.x = __uint_as_float(f2tf(v.x));
        w.y = __uint_as_float(f2tf(v.y));
        w.z = __uint_as_float(f2tf(v.z));
        w.w = __uint_as_float(f2tf(v.w));
        dst[i] = w;
    }
}

// ---------------------------------------------------------------------------
// Kernel 1: tf32 GEMM, C[M,N] = A[M,768] * B[N,768]^T, inputs pre-rounded.
// CTA tile 128x256, BK=32, 512 threads / 16 warps (4m x 4n), warp tile 32x64.
// cp.async double-buffered staging (no cvt), all fragments via ldmatrix.x4.
// MODE 1: A=g_hid_tf, B=g_w_tf (Wq|Wk|Wv), SiLU+round, scatter to g_q/k/v.
// MODE 0: A=g_o, B=g_wo_tf, plain write to Cout.
// ---------------------------------------------------------------------------
constexpr int GLD = 36;                        // smem row pitch (floats), 144B
constexpr int GEMM_SMEM = 2 * (128 + 256) * GLD * 4;   // 110592 B

template<int MODE>
__global__ __launch_bounds__(512, 1)
void gemm_tf32_kernel(float* __restrict__ Cout) {
    extern __shared__ uint32_t sm[];
    uint32_t* As = sm;                          // [2][128*GLD]
    uint32_t* Bs = sm + 2 * 128 * GLD;          // [2][256*GLD]

    const int tid = threadIdx.x;
    const int warp = tid >> 5, lane = tid & 31;
    const int gr = lane >> 2, gc = lane & 3;
    const int m0 = blockIdx.y * 128;
    const int n0g = blockIdx.x * 256;

    const float* Arow = ((MODE == 1) ? g_hid_tf : g_o) + (size_t)m0 * Dc;
    const float* Brow = ((MODE == 1) ? g_w_tf : g_wo_tf) + (size_t)n0g * Dc;

    const int warp_m0 = (warp >> 2) * 32;       // 4 warps in m
    const int warp_n0 = (warp & 3) * 64;        // 4 warps in n

    // ldmatrix lane offsets (bytes)
    const uint32_t laneA = ((lane & 15) * GLD + 4 * (lane >> 4)) * 4;
    const uint32_t laneB = ((((lane >> 3) & 1) * 8 + (lane & 7)) * GLD) * 4
                         + (lane >> 4) * 16;
    const uint32_t AsU = s2u(As), BsU = s2u(Bs);

    auto load_tile = [&](int kt, int buf) {
        uint32_t Ab = AsU + buf * 128 * GLD * 4;
        uint32_t Bb = BsU + buf * 256 * GLD * 4;
#pragma unroll
        for (int i = 0; i < 2; i++) {            // A: 128 rows x 8 chunks
            const int idx = tid + i * 512;
            const int r = idx >> 3;
            const int cB = (idx & 7) << 4;       // bytes
            cpa16(Ab + r * GLD * 4 + cB, Arow + (size_t)r * Dc + kt * 32 + (cB >> 2));
        }
#pragma unroll
        for (int i = 0; i < 4; i++) {            // B: 256 rows x 8 chunks
            const int idx = tid + i * 512;
            const int r = idx >> 3;
            const int cB = (idx & 7) << 4;
            cpa16(Bb + r * GLD * 4 + cB, Brow + (size_t)r * Dc + kt * 32 + (cB >> 2));
        }
        asm volatile("cp.async.commit_group;");
    };

    float c[2][8][4] = {};                       // [mt][nt][frag]

    load_tile(0, 0);

    for (int kt = 0; kt < 24; kt++) {
        const int buf = kt & 1;
        if (kt < 23) {
            load_tile(kt + 1, buf ^ 1);
            asm volatile("cp.async.wait_group 1;");
        } else {
            asm volatile("cp.async.wait_group 0;");
        }
        __syncthreads();

        const uint32_t AbU = AsU + buf * 128 * GLD * 4;
        const uint32_t BbU = BsU + buf * 256 * GLD * 4;
#pragma unroll
        for (int kk = 0; kk < 4; kk++) {
            const int klo = kk * 8;
            uint32_t a[2][4], bf[4][4];
#pragma unroll
            for (int mt = 0; mt < 2; mt++)
                lm4(a[mt][0], a[mt][1], a[mt][2], a[mt][3],
                    AbU + ((warp_m0 + mt * 16) * GLD + klo) * 4 + laneA);
#pragma unroll
            for (int g = 0; g < 4; g++)
                lm4(bf[g][0], bf[g][1], bf[g][2], bf[g][3],
                    BbU + ((warp_n0 + g * 16) * GLD + klo) * 4 + laneB);
#pragma unroll
            for (int mt = 0; mt < 2; mt++)
#pragma unroll
                for (int nt = 0; nt < 8; nt++) {
                    const int g = nt >> 1, hf = nt & 1;
                    mma_tf32(c[mt][nt], a[mt][0], a[mt][1], a[mt][2], a[mt][3],
                             bf[g][hf], bf[g][2 + hf]);
                }
        }
        __syncthreads();
    }

    if (MODE == 0) {
#pragma unroll
        for (int mt = 0; mt < 2; mt++)
#pragma unroll
            for (int nt = 0; nt < 8; nt++) {
                const int row = m0 + warp_m0 + mt * 16 + gr;
                const int col = n0g + warp_n0 + nt * 8 + 2 * gc;
                Cout[(size_t)(row    ) * Dc + col    ] = c[mt][nt][0];
                Cout[(size_t)(row    ) * Dc + col + 1] = c[mt][nt][1];
                Cout[(size_t)(row + 8) * Dc + col    ] = c[mt][nt][2];
                Cout[(size_t)(row + 8) * Dc + col + 1] = c[mt][nt][3];
            }
    } else {
        const int which = n0g / Dc;              // 256-tiles never straddle
        float* dst = (which == 0) ? g_q : (which == 1) ? g_k : g_v;
        const int n0 = n0g % Dc;
#pragma unroll
        for (int mt = 0; mt < 2; mt++)
#pragma unroll
            for (int nt = 0; nt < 8; nt++)
#pragma unroll
                for (int half = 0; half < 2; half++)
#pragma unroll
                    for (int e = 0; e < 2; e++) {
                        const int row = m0 + warp_m0 + mt * 16 + half * 8 + gr;
                        const int colL = n0 + warp_n0 + nt * 8 + 2 * gc + e;
                        const int h = colL >> 6, d = colL & 63;
                        const int b = row >> 11, l = row & 2047;
                        dst[(((size_t)b * Hc + h) * Lc + l) * HDc + d] =
                            __uint_as_float(f2tf(silu_f(c[mt][nt][half * 2 + e])));
                    }
    }
}

// ---------------------------------------------------------------------------
// Kernel 2: in-place RoPE on g_q and g_k; outputs rounded to tf32.
// ---------------------------------------------------------------------------
__global__ void rope_kernel(const float* __restrict__ cosp,
                            const float* __restrict__ sinp) {
    const int idx = blockIdx.x * blockDim.x + threadIdx.x;
    const int pair = idx & 31;
    const int t = idx >> 5;
    const int nrows = BH * Lc;
    const int which = t / nrows;
    const int row = t % nrows;
    float* p = which ? g_k : g_q;

    const int l = row % Lc;
    const int b = (row / Lc) / Hc;

    const size_t cbase = ((size_t)b * Lc + l) * HDc;
    const float c1 = cosp[cbase + pair];
    const float c2 = cosp[cbase + pair + 32];
    const float s1 = sinp[cbase + pair];
    const float s2 = sinp[cbase + pair + 32];

    const size_t base = (size_t)row * HDc;
    const float x1 = p[base + pair];
    const float x2 = p[base + pair + 32];
    p[base + pair]      = __uint_as_float(f2tf(x1 * c1 - x2 * s1));
    p[base + pair + 32] = __uint_as_float(f2tf(x2 * c2 + x1 * s2));
}

// ---------------------------------------------------------------------------
// Kernel 3: causal attention, mma.sync tf32. Inputs pre-rounded (no cvt in
// staging). K/V fragments via ldmatrix.x4. 128-row q tiles, 512 threads,
// 16 warps (8m x 2n), qt-descending schedule.
// ---------------------------------------------------------------------------
constexpr int ALD = 68;                          // smem row pitch (floats)
constexpr int ATTN_SMEM = (64 + 64 + 128) * ALD * 4;  // Ks,Vt,Ss = 69632 B
constexpr int QTILES = Lc / 128;                 // 16

__global__ __launch_bounds__(512, 1)
void attn_mma_kernel(float* __restrict__ attn_out) {
    extern __shared__ uint32_t sm[];
    uint32_t* Ks = sm;                    // [64][ALD] tf32
    uint32_t* Vt = Ks + 64 * ALD;         // [d=64][ALD] tf32, transposed
    float*    Ss = (float*)(Vt + 64 * ALD);   // [128][ALD] f32

    const int tid = threadIdx.x;
    const int warp = tid >> 5, lane = tid & 31;
    const int gr = lane >> 2, gc = lane & 3;
    const int qt = QTILES - 1 - (int)blockIdx.x / BH;
    const int bh = (int)blockIdx.x % BH;
    const int q0 = qt * 128;

    const int warp_m0 = (warp >> 1) * 16;   // 8 warps in m
    const int warp_n0 = (warp & 1) * 32;    // 2 warps in n

    const uint32_t laneA = ((lane & 15) * ALD + 4 * (lane >> 4)) * 4;
    const uint32_t laneB4 = ((((lane >> 3) & 1) * 8 + (lane & 7)) * ALD) * 4
                          + (lane >> 4) * 16;
    const uint32_t KsU = s2u(Ks), VtU = s2u(Vt), SsU = s2u(Ss);

    const float* Qg = g_q + (size_t)bh * Lc * HDc;
    const float* Kg = g_k + (size_t)bh * Lc * HDc;
    const float* Vg = g_v + (size_t)bh * Lc * HDc;
    float* attn_base = attn_out + (size_t)bh * Lc * Lc;

    // Stage Q (pre-rounded) into Ss area, preload Q fragments.
#pragma unroll
    for (int i = 0; i < 4; i++) {
        const int idx = tid + i * 512;
        const int r = idx >> 4;
        const int c4 = (idx & 15) << 2;
        *(float4*)&Ss[r * ALD + c4] = *(const float4*)&Qg[(size_t)(q0 + r) * HDc + c4];
    }
    __syncthreads();

    uint32_t qf[8][4];
#pragma unroll
    for (int kk = 0; kk < 8; kk++)
        lm4(qf[kk][0], qf[kk][1], qf[kk][2], qf[kk][3],
            SsU + (warp_m0 * ALD + kk * 8) * 4 + laneA);
    __syncthreads();

    float o[4][4] = {};
    const int ktn = 2 * qt + 2;

    for (int kt = 0; kt < ktn; kt++) {
        if (kt > 0) __syncthreads();
        // Stage K rows (pure copy)
#pragma unroll
        for (int i = 0; i < 2; i++) {
            const int idx = tid + i * 512;
            const int r = idx >> 4;
            const int c4 = (idx & 15) << 2;
            *(uint4*)&Ks[r * ALD + c4] =
                *(const uint4*)&Kg[(size_t)(kt * 64 + r) * HDc + c4];
        }
        // Stage V transposed (pure copy): Vt[d][k]
#pragma unroll
        for (int i = 0; i < 2; i++) {
            const int idx = tid + i * 512;
            const int d = idx & 63;
            const int rg = idx >> 6;
            const int kb = kt * 64 + rg * 4;
            uint4 vv;
            vv.x = ((const uint32_t*)Vg)[(size_t)(kb + 0) * HDc + d];
            vv.y = ((const uint32_t*)Vg)[(size_t)(kb + 1) * HDc + d];
            vv.z = ((const uint32_t*)Vg)[(size_t)(kb + 2) * HDc + d];
            vv.w = ((const uint32_t*)Vg)[(size_t)(kb + 3) * HDc + d];
            *(uint4*)&Vt[d * ALD + rg * 4] = vv;
        }
        __syncthreads();

        // S = Q K^T
        float s[4][4] = {};
#pragma unroll
        for (int kk = 0; kk < 8; kk++) {
            uint32_t bf[2][4];
#pragma unroll
            for (int g = 0; g < 2; g++)
                lm4(bf[g][0], bf[g][1], bf[g][2], bf[g][3],
                    KsU + ((warp_n0 + g * 16) * ALD + kk * 8) * 4 + laneB4);
#pragma unroll
            for (int nt = 0; nt < 4; nt++) {
                const int g = nt >> 1, hf = nt & 1;
                mma_tf32(s[nt], qf[kk][0], qf[kk][1], qf[kk][2], qf[kk][3],
                         bf[g][hf], bf[g][2 + hf]);
            }
        }

        // mask + silu/L -> Ss
#pragma unroll
        for (int nt = 0; nt < 4; nt++)
#pragma unroll
            for (int half = 0; half < 2; half++)
#pragma unroll
                for (int e = 0; e < 2; e++) {
                    const int row = warp_m0 + half * 8 + gr;
                    const int col = warp_n0 + nt * 8 + 2 * gc + e;
                    const int q = q0 + row;
                    const int k = kt * 64 + col;
                    const float x = s[nt][half * 2 + e];
                    Ss[row * ALD + col] =
                        (k <= q) ? silu_f(x) * (1.0f / Lc) : 0.0f;
                }
        __syncthreads();

        // attn gmem write (float4)
#pragma unroll
        for (int i = 0; i < 4; i++) {
            const int idx = tid + i * 512;
            const int r = idx >> 4;
            const int c4 = (idx & 15) << 2;
            *(float4*)&attn_base[(size_t)(q0 + r) * Lc + kt * 64 + c4] =
                *(const float4*)&Ss[r * ALD + c4];
        }

        // O += S @ V
#pragma unroll
        for (int kk = 0; kk < 8; kk++) {
            const int klo = kk * 8;
            uint32_t a[4], bf[2][4];
            lm4(a[0], a[1], a[2], a[3],
                SsU + (warp_m0 * ALD + klo) * 4 + laneA);
#pragma unroll
            for (int j = 0; j < 4; j++)
                a[j] = f2tf(__uint_as_float(a[j]));
#pragma unroll
            for (int g = 0; g < 2; g++)
                lm4(bf[g][0], bf[g][1], bf[g][2], bf[g][3],
                    VtU + ((warp_n0 + g * 16) * ALD + klo) * 4 + laneB4);
#pragma unroll
            for (int nt = 0; nt < 4; nt++) {
                const int g = nt >> 1, hf = nt & 1;
                mma_tf32(o[nt], a[0], a[1], a[2], a[3], bf[g][hf], bf[g][2 + hf]);
            }
        }
    }

    // Zero-fill strictly-upper region (k >= q0+128)
    const int zstart = q0 + 128;
    const int zcols = Lc - zstart;
    if (zcols > 0) {
        const int row4 = zcols >> 2;
        const int tot4 = 128 * row4;
        for (int e = tid; e < tot4; e += 512) {
            const int row = e / row4;
            const int c4 = (e % row4) << 2;
            *(float4*)&attn_base[(size_t)(q0 + row) * Lc + zstart + c4] =
                make_float4(0.f, 0.f, 0.f, 0.f);
        }
    }

    // Write O (tf32-rounded, feeds cp.async output projection)
    const int b = bh / Hc;
    const int h = bh % Hc;
#pragma unroll
    for (int nt = 0; nt < 4; nt++)
#pragma unroll
        for (int half = 0; half < 2; half++)
#pragma unroll
            for (int e = 0; e < 2; e++) {
                const int row = q0 + warp_m0 + half * 8 + gr;
                const int d = warp_n0 + nt * 8 + 2 * gc + e;
                g_o[((size_t)b * Lc + row) * Dc + h * HDc + d] =
                    __uint_as_float(f2tf(o[nt][half * 2 + e]));
            }
}

// ---------------------------------------------------------------------------
// Launch. Inputs: hidden_states, attention_mask, cos, sin, Wq, Wk, Wv, Wo.
// Output: [attn_output (B*L*D) | attn (B*H*L*L)]. Mask handled analytically.
// ---------------------------------------------------------------------------
extern "C" void kernel_launch(void* const* d_in, const int* in_sizes, int n_in,
                              void* d_out, int out_size) {
    const float* hidden = (const float*)d_in[0];
    const float* cosp   = (const float*)d_in[2];
    const float* sinp   = (const float*)d_in[3];
    const float* Wq     = (const float*)d_in[4];
    const float* Wk     = (const float*)d_in[5];
    const float* Wv     = (const float*)d_in[6];
    const float* Wo     = (const float*)d_in[7];

    float* out = (float*)d_out;
    float* attn_out = out + (size_t)Bc * Lc * Dc;

    cudaFuncSetAttribute(gemm_tf32_kernel<1>,
                         cudaFuncAttributeMaxDynamicSharedMemorySize, GEMM_SMEM);
    cudaFuncSetAttribute(gemm_tf32_kernel<0>,
                         cudaFuncAttributeMaxDynamicSharedMemorySize, GEMM_SMEM);
    cudaFuncSetAttribute(attn_mma_kernel,
                         cudaFuncAttributeMaxDynamicSharedMemorySize, ATTN_SMEM);

    // 0) Pre-round inputs to tf32 (RNA): hot loops become cvt-free.
    float* g_hid_p; cudaGetSymbolAddress((void**)&g_hid_p, g_hid_tf);
    float* g_w_p;   cudaGetSymbolAddress((void**)&g_w_p,   g_w_tf);
    float* g_wo_p;  cudaGetSymbolAddress((void**)&g_wo_p,  g_wo_tf);
    const int W4 = Dc * Dc / 4;
    cvt_tf32_kernel<<<(Mrows * Dc / 4 + 255) / 256, 256>>>(
        (const float4*)hidden, (float4*)g_hid_p, Mrows * Dc / 4);
    cvt_tf32_kernel<<<(W4 + 255) / 256, 256>>>(
        (const float4*)Wq, (float4*)g_w_p, W4);
    cvt_tf32_kernel<<<(W4 + 255) / 256, 256>>>(
        (const float4*)Wk, (float4*)(g_w_p + (size_t)Dc * Dc), W4);
    cvt_tf32_kernel<<<(W4 + 255) / 256, 256>>>(
        (const float4*)Wv, (float4*)(g_w_p + (size_t)2 * Dc * Dc), W4);
    cvt_tf32_kernel<<<(W4 + 255) / 256, 256>>>(
        (const float4*)Wo, (float4*)g_wo_p, W4);

    // 1) QKV projections + SiLU (9 x 32 CTAs of 128x256)
    gemm_tf32_kernel<1><<<dim3(3 * Dc / 256, Mrows / 128), 512, GEMM_SMEM>>>(nullptr);

    // 2) RoPE on q,k
    {
        const int total = 2 * BH * Lc * 32;
        rope_kernel<<<total / 256, 256>>>(cosp, sinp);
    }

    // 3) Attention (qt-descending 1D schedule)
    attn_mma_kernel<<<QTILES * BH, 512, ATTN_SMEM>>>(attn_out);

    // 4) Output projection (3 x 32 CTAs of 128x256, single wave)
    gemm_tf32_kernel<0><<<dim3(Dc / 256, Mrows / 128), 512, GEMM_SMEM>>>(out);
}

// round 10
// speedup vs baseline: 1.3409x; 1.0648x over previous
#include <cuda_runtime.h>
#include <cuda_bf16.h>
#include <cstdint>

// Problem constants
constexpr int Bc  = 2;
constexpr int Lc  = 2048;
constexpr int Dc  = 768;
constexpr int Hc  = 12;
constexpr int HDc = 64;
constexpr int BH  = Bc * Hc;            // 24
constexpr int Mrows = Bc * Lc;          // 4096

// Scratch (device globals; no allocation allowed)
__device__ __align__(128) float g_q[(size_t)BH * Lc * HDc];   // [b,h,l,d] tf32-rounded (post-RoPE)
__device__ __align__(128) float g_k[(size_t)BH * Lc * HDc];   // tf32-rounded (post-RoPE)
__device__ __align__(128) float g_v[(size_t)BH * Lc * HDc];   // tf32-rounded
__device__ __align__(128) float g_o[(size_t)Bc * Lc * Dc];    // [b,l,h*64+d] tf32-rounded
__device__ __align__(128) float g_hid_tf[(size_t)Mrows * Dc];   // rounded hidden
__device__ __align__(128) float g_w_tf[(size_t)3 * Dc * Dc];    // rounded Wq|Wk|Wv
__device__ __align__(128) float g_wo_tf[(size_t)Dc * Dc];       // rounded Wo

__device__ __forceinline__ float silu_f(float x) {
    return x / (1.0f + __expf(-x));
}

__device__ __forceinline__ uint32_t f2tf(float x) {
    uint32_t r;
    asm("cvt.rna.tf32.f32 %0, %1;" : "=r"(r) : "f"(x));
    return r;
}

__device__ __forceinline__ uint32_t s2u(const void* p) {
    return (uint32_t)__cvta_generic_to_shared(p);
}

__device__ __forceinline__ void lm4(uint32_t& r0, uint32_t& r1,
                                    uint32_t& r2, uint32_t& r3, uint32_t addr) {
    asm volatile("ldmatrix.sync.aligned.m8n8.x4.shared.b16 {%0,%1,%2,%3},[%4];"
                 : "=r"(r0), "=r"(r1), "=r"(r2), "=r"(r3) : "r"(addr));
}

__device__ __forceinline__ void mma_tf32(float c[4],
                                         uint32_t a0, uint32_t a1, uint32_t a2, uint32_t a3,
                                         uint32_t b0, uint32_t b1) {
    asm volatile(
        "mma.sync.aligned.m16n8k8.row.col.f32.tf32.tf32.f32 "
        "{%0,%1,%2,%3},{%4,%5,%6,%7},{%8,%9},{%0,%1,%2,%3};"
        : "+f"(c[0]), "+f"(c[1]), "+f"(c[2]), "+f"(c[3])
        : "r"(a0), "r"(a1), "r"(a2), "r"(a3), "r"(b0), "r"(b1));
}

__device__ __forceinline__ void cpa16(uint32_t s, const void* g) {
    asm volatile("cp.async.cg.shared.global [%0], [%1], 16;" :: "r"(s), "l"(g));
}

// ---------------------------------------------------------------------------
// Kernel 0: single fused tf32-rounding pass over hidden + 4 weights.
// ---------------------------------------------------------------------------
constexpr int HID4 = Mrows * Dc / 4;    // 786432
constexpr int W4   = Dc * Dc / 4;       // 147456
constexpr int CVT_TOT = HID4 + 4 * W4;  // 1376256

__global__ void cvt_all_kernel(const float4* __restrict__ hid,
                               const float4* __restrict__ wq,
                               const float4* __restrict__ wk,
                               const float4* __restrict__ wv,
                               const float4* __restrict__ wo) {
    const int i = blockIdx.x * blockDim.x + threadIdx.x;
    if (i >= CVT_TOT) return;
    const float4* src;
    float4* dst;
    int off;
    if (i < HID4) {
        src = hid; dst = (float4*)g_hid_tf; off = i;
    } else {
        const int j = i - HID4;
        const int w = j / W4;
        off = j - w * W4;
        src = (w == 0) ? wq : (w == 1) ? wk : (w == 2) ? wv : wo;
        dst = (w < 3) ? (float4*)g_w_tf + (size_t)w * W4 : (float4*)g_wo_tf;
    }
    float4 v = src[off];
    float4 r;
    r.x = __uint_as_float(f2tf(v.x));
    r.y = __uint_as_float(f2tf(v.y));
    r.z = __uint_as_float(f2tf(v.z));
    r.w = __uint_as_float(f2tf(v.w));
    dst[off] = r;
}

// ---------------------------------------------------------------------------
// Kernel 1: tf32 GEMM, C[M,N] = A[M,768] * B[N,768]^T, inputs pre-rounded.
// CTA tile 128x256, BK=32, 512 threads / 16 warps (4m x 4n), warp tile 32x64.
// cp.async double-buffered staging, all fragments via ldmatrix.x4.
// MODE 1: A=g_hid_tf, B=g_w_tf (Wq|Wk|Wv). Epilogue: SiLU, then for q/k the
//         FUSED RoPE (each warp owns a full head; d and d+32 are in the same
//         thread at nt and nt+4), round, scatter to g_q/g_k/g_v.
// MODE 0: A=g_o, B=g_wo_tf, plain write to Cout.
// ---------------------------------------------------------------------------
constexpr int GLD = 36;                        // smem row pitch (floats), 144B
constexpr int GEMM_SMEM = 2 * (128 + 256) * GLD * 4;   // 110592 B

template<int MODE>
__global__ __launch_bounds__(512, 1)
void gemm_tf32_kernel(float* __restrict__ Cout,
                      const float* __restrict__ cosp,
                      const float* __restrict__ sinp) {
    extern __shared__ uint32_t sm[];
    uint32_t* As = sm;                          // [2][128*GLD]
    uint32_t* Bs = sm + 2 * 128 * GLD;          // [2][256*GLD]

    const int tid = threadIdx.x;
    const int warp = tid >> 5, lane = tid & 31;
    const int gr = lane >> 2, gc = lane & 3;
    const int m0 = blockIdx.y * 128;
    const int n0g = blockIdx.x * 256;

    const float* Arow = ((MODE == 1) ? g_hid_tf : g_o) + (size_t)m0 * Dc;
    const float* Brow = ((MODE == 1) ? g_w_tf : g_wo_tf) + (size_t)n0g * Dc;

    const int warp_m0 = (warp >> 2) * 32;       // 4 warps in m
    const int warp_n0 = (warp & 3) * 64;        // 4 warps in n

    const uint32_t laneA = ((lane & 15) * GLD + 4 * (lane >> 4)) * 4;
    const uint32_t laneB = ((((lane >> 3) & 1) * 8 + (lane & 7)) * GLD) * 4
                         + (lane >> 4) * 16;
    const uint32_t AsU = s2u(As), BsU = s2u(Bs);

    auto load_tile = [&](int kt, int buf) {
        uint32_t Ab = AsU + buf * 128 * GLD * 4;
        uint32_t Bb = BsU + buf * 256 * GLD * 4;
#pragma unroll
        for (int i = 0; i < 2; i++) {            // A: 128 rows x 8 chunks
            const int idx = tid + i * 512;
            const int r = idx >> 3;
            const int cB = (idx & 7) << 4;
            cpa16(Ab + r * GLD * 4 + cB, Arow + (size_t)r * Dc + kt * 32 + (cB >> 2));
        }
#pragma unroll
        for (int i = 0; i < 4; i++) {            // B: 256 rows x 8 chunks
            const int idx = tid + i * 512;
            const int r = idx >> 3;
            const int cB = (idx & 7) << 4;
            cpa16(Bb + r * GLD * 4 + cB, Brow + (size_t)r * Dc + kt * 32 + (cB >> 2));
        }
        asm volatile("cp.async.commit_group;");
    };

    float c[2][8][4] = {};                       // [mt][nt][frag]

    load_tile(0, 0);

    for (int kt = 0; kt < 24; kt++) {
        const int buf = kt & 1;
        if (kt < 23) {
            load_tile(kt + 1, buf ^ 1);
            asm volatile("cp.async.wait_group 1;");
        } else {
            asm volatile("cp.async.wait_group 0;");
        }
        __syncthreads();

        const uint32_t AbU = AsU + buf * 128 * GLD * 4;
        const uint32_t BbU = BsU + buf * 256 * GLD * 4;
#pragma unroll
        for (int kk = 0; kk < 4; kk++) {
            const int klo = kk * 8;
            uint32_t a[2][4], bf[4][4];
#pragma unroll
            for (int mt = 0; mt < 2; mt++)
                lm4(a[mt][0], a[mt][1], a[mt][2], a[mt][3],
                    AbU + ((warp_m0 + mt * 16) * GLD + klo) * 4 + laneA);
#pragma unroll
            for (int g = 0; g < 4; g++)
                lm4(bf[g][0], bf[g][1], bf[g][2], bf[g][3],
                    BbU + ((warp_n0 + g * 16) * GLD + klo) * 4 + laneB);
#pragma unroll
            for (int mt = 0; mt < 2; mt++)
#pragma unroll
                for (int nt = 0; nt < 8; nt++) {
                    const int g = nt >> 1, hf = nt & 1;
                    mma_tf32(c[mt][nt], a[mt][0], a[mt][1], a[mt][2], a[mt][3],
                             bf[g][hf], bf[g][2 + hf]);
                }
        }
        __syncthreads();
    }

    if (MODE == 0) {
#pragma unroll
        for (int mt = 0; mt < 2; mt++)
#pragma unroll
            for (int nt = 0; nt < 8; nt++) {
                const int row = m0 + warp_m0 + mt * 16 + gr;
                const int col = n0g + warp_n0 + nt * 8 + 2 * gc;
                Cout[(size_t)(row    ) * Dc + col    ] = c[mt][nt][0];
                Cout[(size_t)(row    ) * Dc + col + 1] = c[mt][nt][1];
                Cout[(size_t)(row + 8) * Dc + col    ] = c[mt][nt][2];
                Cout[(size_t)(row + 8) * Dc + col + 1] = c[mt][nt][3];
            }
    } else {
        const int which = n0g / Dc;              // 256-tiles never straddle
        const int n0 = n0g % Dc;
        if (which < 2) {
            // ---- fused SiLU + RoPE for q/k ----
            float* dst = which ? g_k : g_q;
            float* cosS = (float*)sm;            // [128][68]
            float* sinS = cosS + 128 * 68;
            // cos/sin row index == global m row (cos layout [b,l,64], m=b*2048+l)
#pragma unroll
            for (int i = 0; i < 4; i++) {
                const int idx = tid + i * 512;   // 2048 float4
                const int r = idx >> 4;
                const int c4 = (idx & 15) << 2;
                *(float4*)&cosS[r * 68 + c4] =
                    *(const float4*)&cosp[(size_t)(m0 + r) * HDc + c4];
                *(float4*)&sinS[r * 68 + c4] =
                    *(const float4*)&sinp[(size_t)(m0 + r) * HDc + c4];
            }
            __syncthreads();
            const int h = (n0 + warp_n0) >> 6;
#pragma unroll
            for (int mt = 0; mt < 2; mt++)
#pragma unroll
                for (int half = 0; half < 2; half++)
#pragma unroll
                    for (int nt = 0; nt < 4; nt++)
#pragma unroll
                        for (int e = 0; e < 2; e++) {
                            const int r = warp_m0 + mt * 16 + half * 8 + gr;
                            const int d = nt * 8 + 2 * gc + e;
                            const float x1 = silu_f(c[mt][nt    ][half * 2 + e]);
                            const float x2 = silu_f(c[mt][nt + 4][half * 2 + e]);
                            const float c1 = cosS[r * 68 + d];
                            const float s1 = sinS[r * 68 + d];
                            const float c2 = cosS[r * 68 + d + 32];
                            const float s2 = sinS[r * 68 + d + 32];
                            const int m = m0 + r, b = m >> 11, l = m & 2047;
                            const size_t base = (((size_t)b * Hc + h) * Lc + l) * HDc;
                            dst[base + d] =
                                __uint_as_float(f2tf(x1 * c1 - x2 * s1));
                            dst[base + d + 32] =
                                __uint_as_float(f2tf(x2 * c2 + x1 * s2));
                        }
        } else {
            // ---- v: SiLU only ----
#pragma unroll
            for (int mt = 0; mt < 2; mt++)
#pragma unroll
                for (int nt = 0; nt < 8; nt++)
#pragma unroll
                    for (int half = 0; half < 2; half++)
#pragma unroll
                        for (int e = 0; e < 2; e++) {
                            const int row = m0 + warp_m0 + mt * 16 + half * 8 + gr;
                            const int colL = n0 + warp_n0 + nt * 8 + 2 * gc + e;
                            const int hh = colL >> 6, d = colL & 63;
                            const int b = row >> 11, l = row & 2047;
                            g_v[(((size_t)b * Hc + hh) * Lc + l) * HDc + d] =
                                __uint_as_float(f2tf(silu_f(c[mt][nt][half * 2 + e])));
                        }
        }
    }
}

// ---------------------------------------------------------------------------
// Kernel 2: causal attention, mma.sync tf32. cp.async double-buffered K/V
// staging (V transposed smem->smem, overlapped with QK MMAs). 128-row q
// tiles, 512 threads, 16 warps (8m x 2n), qt-descending schedule.
// ---------------------------------------------------------------------------
constexpr int ALD = 68;                              // smem row pitch (floats)
constexpr int ATTN_SMEM = (5 * 64 + 128) * ALD * 4;  // Kb2,Vb2,Vt,Ss = 121856 B
constexpr int QTILES = Lc / 128;                     // 16

__global__ __launch_bounds__(512, 1)
void attn_mma_kernel(float* __restrict__ attn_out) {
    extern __shared__ uint32_t sm[];
    uint32_t* Kb = sm;                        // [2][64][ALD] K rows
    uint32_t* Vb = sm + 2 * 64 * ALD;         // [2][64][ALD] V rows (raw)
    uint32_t* Vt = sm + 4 * 64 * ALD;         // [64][ALD]   V transposed
    float*    Ss = (float*)(sm + 5 * 64 * ALD);   // [128][ALD]

    const int tid = threadIdx.x;
    const int warp = tid >> 5, lane = tid & 31;
    const int gr = lane >> 2, gc = lane & 3;
    const int qt = QTILES - 1 - (int)blockIdx.x / BH;
    const int bh = (int)blockIdx.x % BH;
    const int q0 = qt * 128;

    const int warp_m0 = (warp >> 1) * 16;   // 8 warps in m
    const int warp_n0 = (warp & 1) * 32;    // 2 warps in n

    const uint32_t laneA = ((lane & 15) * ALD + 4 * (lane >> 4)) * 4;
    const uint32_t laneB4 = ((((lane >> 3) & 1) * 8 + (lane & 7)) * ALD) * 4
                          + (lane >> 4) * 16;
    const uint32_t KbU = s2u(Kb), VtU = s2u(Vt), SsU = s2u(Ss);

    const float* Qg = g_q + (size_t)bh * Lc * HDc;
    const float* Kg = g_k + (size_t)bh * Lc * HDc;
    const float* Vg = g_v + (size_t)bh * Lc * HDc;
    float* attn_base = attn_out + (size_t)bh * Lc * Lc;

    auto load_kv = [&](int kt, int buf) {
        const uint32_t kB = KbU + buf * 64 * ALD * 4;
        const uint32_t vB = kB + 2 * 64 * ALD * 4;   // Vb mirrors Kb layout
#pragma unroll
        for (int i = 0; i < 2; i++) {
            const int idx = tid + i * 512;           // 1024 chunks of 16B
            const int r = idx >> 4;
            const int cB = (idx & 15) << 4;
            cpa16(kB + r * ALD * 4 + cB, Kg + (size_t)(kt * 64 + r) * HDc + (cB >> 2));
            cpa16(vB + r * ALD * 4 + cB, Vg + (size_t)(kt * 64 + r) * HDc + (cB >> 2));
        }
        asm volatile("cp.async.commit_group;");
    };

    load_kv(0, 0);

    // Stage Q (pre-rounded) into Ss, preload Q fragments.
#pragma unroll
    for (int i = 0; i < 4; i++) {
        const int idx = tid + i * 512;
        const int r = idx >> 4;
        const int c4 = (idx & 15) << 2;
        *(float4*)&Ss[r * ALD + c4] = *(const float4*)&Qg[(size_t)(q0 + r) * HDc + c4];
    }
    __syncthreads();

    uint32_t qf[8][4];
#pragma unroll
    for (int kk = 0; kk < 8; kk++)
        lm4(qf[kk][0], qf[kk][1], qf[kk][2], qf[kk][3],
            SsU + (warp_m0 * ALD + kk * 8) * 4 + laneA);

    float o[4][4] = {};
    const int ktn = 2 * qt + 2;

    for (int kt = 0; kt < ktn; kt++) {
        const int cur = kt & 1;
        if (kt + 1 < ktn) {
            load_kv(kt + 1, cur ^ 1);
            asm volatile("cp.async.wait_group 1;");
        } else {
            asm volatile("cp.async.wait_group 0;");
        }
        __syncthreads();      // buffers[cur] ready; prev iter's Ss/Vt reads done

        // Transpose Vb[cur] -> Vt (LDS conflict-free; STS.128 per 8-lane wf ok)
        {
            const uint32_t* Vbp = Vb + cur * 64 * ALD;
            const int d = tid & 63;
            const int rg = tid >> 6;          // 0..7, k-base rg*8
            uint32_t t0[4], t1[4];
#pragma unroll
            for (int j = 0; j < 4; j++) t0[j] = Vbp[(rg * 8 + j) * ALD + d];
#pragma unroll
            for (int j = 0; j < 4; j++) t1[j] = Vbp[(rg * 8 + 4 + j) * ALD + d];
            *(uint4*)&Vt[d * ALD + rg * 8]     = *(uint4*)t0;
            *(uint4*)&Vt[d * ALD + rg * 8 + 4] = *(uint4*)t1;
        }

        // S = Q K^T from Kb[cur]
        const uint32_t kBU = KbU + cur * 64 * ALD * 4;
        float s[4][4] = {};
#pragma unroll
        for (int kk = 0; kk < 8; kk++) {
            uint32_t bf[2][4];
#pragma unroll
            for (int g = 0; g < 2; g++)
                lm4(bf[g][0], bf[g][1], bf[g][2], bf[g][3],
                    kBU + ((warp_n0 + g * 16) * ALD + kk * 8) * 4 + laneB4);
#pragma unroll
            for (int nt = 0; nt < 4; nt++) {
                const int g = nt >> 1, hf = nt & 1;
                mma_tf32(s[nt], qf[kk][0], qf[kk][1], qf[kk][2], qf[kk][3],
                         bf[g][hf], bf[g][2 + hf]);
            }
        }

        // mask + silu/L -> Ss
#pragma unroll
        for (int nt = 0; nt < 4; nt++)
#pragma unroll
            for (int half = 0; half < 2; half++)
#pragma unroll
                for (int e = 0; e < 2; e++) {
                    const int row = warp_m0 + half * 8 + gr;
                    const int col = warp_n0 + nt * 8 + 2 * gc + e;
                    const int q = q0 + row;
                    const int k = kt * 64 + col;
                    const float x = s[nt][half * 2 + e];
                    Ss[row * ALD + col] =
                        (k <= q) ? silu_f(x) * (1.0f / Lc) : 0.0f;
                }
        __syncthreads();      // Vt + Ss ready

        // attn gmem write (float4)
#pragma unroll
        for (int i = 0; i < 4; i++) {
            const int idx = tid + i * 512;
            const int r = idx >> 4;
            const int c4 = (idx & 15) << 2;
            *(float4*)&attn_base[(size_t)(q0 + r) * Lc + kt * 64 + c4] =
                *(const float4*)&Ss[r * ALD + c4];
        }

        // O += S @ V
#pragma unroll
        for (int kk = 0; kk < 8; kk++) {
            const int klo = kk * 8;
            uint32_t a[4], bf[2][4];
            lm4(a[0], a[1], a[2], a[3],
                SsU + (warp_m0 * ALD + klo) * 4 + laneA);
#pragma unroll
            for (int j = 0; j < 4; j++)
                a[j] = f2tf(__uint_as_float(a[j]));
#pragma unroll
            for (int g = 0; g < 2; g++)
                lm4(bf[g][0], bf[g][1], bf[g][2], bf[g][3],
                    VtU + ((warp_n0 + g * 16) * ALD + klo) * 4 + laneB4);
#pragma unroll
            for (int nt = 0; nt < 4; nt++) {
                const int g = nt >> 1, hf = nt & 1;
                mma_tf32(o[nt], a[0], a[1], a[2], a[3], bf[g][hf], bf[g][2 + hf]);
            }
        }
    }

    // Zero-fill strictly-upper region (k >= q0+128)
    const int zstart = q0 + 128;
    const int zcols = Lc - zstart;
    if (zcols > 0) {
        const int row4 = zcols >> 2;
        const int tot4 = 128 * row4;
        for (int e = tid; e < tot4; e += 512) {
            const int row = e / row4;
            const int c4 = (e % row4) << 2;
            *(float4*)&attn_base[(size_t)(q0 + row) * Lc + zstart + c4] =
                make_float4(0.f, 0.f, 0.f, 0.f);
        }
    }

    // Write O (tf32-rounded, feeds cp.async output projection)
    const int b = bh / Hc;
    const int h = bh % Hc;
#pragma unroll
    for (int nt = 0; nt < 4; nt++)
#pragma unroll
        for (int half = 0; half < 2; half++)
#pragma unroll
            for (int e = 0; e < 2; e++) {
                const int row = q0 + warp_m0 + half * 8 + gr;
                const int d = warp_n0 + nt * 8 + 2 * gc + e;
                g_o[((size_t)b * Lc + row) * Dc + h * HDc + d] =
                    __uint_as_float(f2tf(o[nt][half * 2 + e]));
            }
}

// ---------------------------------------------------------------------------
// Launch. Inputs: hidden_states, attention_mask, cos, sin, Wq, Wk, Wv, Wo.
// Output: [attn_output (B*L*D) | attn (B*H*L*L)]. Mask handled analytically.
// ---------------------------------------------------------------------------
extern "C" void kernel_launch(void* const* d_in, const int* in_sizes, int n_in,
                              void* d_out, int out_size) {
    const float* hidden = (const float*)d_in[0];
    const float* cosp   = (const float*)d_in[2];
    const float* sinp   = (const float*)d_in[3];
    const float* Wq     = (const float*)d_in[4];
    const float* Wk     = (const float*)d_in[5];
    const float* Wv     = (const float*)d_in[6];
    const float* Wo     = (const float*)d_in[7];

    float* out = (float*)d_out;
    float* attn_out = out + (size_t)Bc * Lc * Dc;

    cudaFuncSetAttribute(gemm_tf32_kernel<1>,
                         cudaFuncAttributeMaxDynamicSharedMemorySize, GEMM_SMEM);
    cudaFuncSetAttribute(gemm_tf32_kernel<0>,
                         cudaFuncAttributeMaxDynamicSharedMemorySize, GEMM_SMEM);
    cudaFuncSetAttribute(attn_mma_kernel,
                         cudaFuncAttributeMaxDynamicSharedMemorySize, ATTN_SMEM);

    // 0) One fused tf32-rounding pass (hidden + all weights).
    cvt_all_kernel<<<(CVT_TOT + 255) / 256, 256>>>(
        (const float4*)hidden, (const float4*)Wq, (const float4*)Wk,
        (const float4*)Wv, (const float4*)Wo);

    // 1) QKV projections + SiLU + fused RoPE
    gemm_tf32_kernel<1><<<dim3(3 * Dc / 256, Mrows / 128), 512, GEMM_SMEM>>>(
        nullptr, cosp, sinp);

    // 2) Attention (qt-descending 1D schedule, cp.async pipelined)
    attn_mma_kernel<<<QTILES * BH, 512, ATTN_SMEM>>>(attn_out);

    // 3) Output projection
    gemm_tf32_kernel<0><<<dim3(Dc / 256, Mrows / 128), 512, GEMM_SMEM>>>(
        out, nullptr, nullptr);
}